// round 6
// baseline (speedup 1.0000x reference)
#include <cuda_runtime.h>
#include <cuda_bf16.h>
#include <cstdint>

#define DDIM 50
#define MAXK 2048
#define TM   128      // rows per CTA
#define TKT  64       // K-slots per tile
#define PK   72       // smem pitch in bf16 (144B: bank-conflict-free fragments)

// ---------------- static device scratch (pre-split M, two layouts) -----------
__device__ __align__(16) __nv_bfloat16 gMkA[MAXK * 64];   // [slot][d] hi
__device__ __align__(16) __nv_bfloat16 gMkB[MAXK * 64];   // [slot][d] lo
__device__ __align__(16) __nv_bfloat16 gMdA[64 * MAXK];   // [d][slot] hi
__device__ __align__(16) __nv_bfloat16 gMdB[64 * MAXK];   // [d][slot] lo

// ---------------- smem layout (bytes) ----------------------------------------
// Single tile buffer (4 arrays) + persistent per-lane X-fragment stash.
// X hi/lo staging (36864B) overlays the tile buffer during the prologue only.
#define ARR      9216                   // 64 * 144
#define SM_KH    0
#define SM_KL    ARR
#define SM_DH    (2 * ARR)
#define SM_DL    (3 * ARR)
#define SM_STASH (4 * ARR)              // 36864
#define SM_TOTAL (SM_STASH + 256 * 6 * 16)   // + 24576 = 61440
#define SM_XH 0
#define SM_XL (TM * PK * 2)             // 18432 (staging, prologue only)

// ---------------- helpers ----------------------------------------------------
__device__ __forceinline__ uint32_t smem_u32(const void* p) {
    uint32_t a;
    asm("{ .reg .u64 t; cvta.to.shared.u64 t, %1; cvt.u32.u64 %0, t; }" : "=r"(a) : "l"(p));
    return a;
}
__device__ __forceinline__ void sts32(uint32_t addr, uint32_t v) {
    asm volatile("st.shared.b32 [%0], %1;" :: "r"(addr), "r"(v) : "memory");
}
__device__ __forceinline__ uint32_t lds32(uint32_t addr) {
    uint32_t v;
    asm("ld.shared.b32 %0, [%1];" : "=r"(v) : "r"(addr));
    return v;
}
__device__ __forceinline__ void sts128(uint32_t addr, const uint32_t* v) {
    asm volatile("st.shared.v4.b32 [%0], {%1, %2, %3, %4};"
                 :: "r"(addr), "r"(v[0]), "r"(v[1]), "r"(v[2]), "r"(v[3]) : "memory");
}
__device__ __forceinline__ void lds128(uint32_t* v, uint32_t addr) {
    asm("ld.shared.v4.u32 {%0, %1, %2, %3}, [%4];"
        : "=r"(v[0]), "=r"(v[1]), "=r"(v[2]), "=r"(v[3]) : "r"(addr));
}
__device__ __forceinline__ uint32_t pack2(float lo, float hi) {   // -> bf16x2
    uint32_t r;
    asm("{ .reg .b16 l, h; cvt.rn.bf16.f32 l, %1; cvt.rn.bf16.f32 h, %2; mov.b32 %0, {l, h}; }"
        : "=r"(r) : "f"(lo), "f"(hi));
    return r;
}
__device__ __forceinline__ void unpack2(uint32_t w, float& a, float& b) {
    asm("{ .reg .b16 l, h; mov.b32 {l, h}, %2; cvt.f32.bf16 %0, l; cvt.f32.bf16 %1, h; }"
        : "=f"(a), "=f"(b) : "r"(w));
}
__device__ __forceinline__ float bf16_rt(float v) {               // round-trip
    float r;
    asm("{ .reg .b16 t; cvt.rn.bf16.f32 t, %1; cvt.f32.bf16 %0, t; }" : "=f"(r) : "f"(v));
    return r;
}
// D += A * B   (m16n8k16, row.col, bf16 in, f32 accum)
__device__ __forceinline__ void mma(float* d, const uint32_t* a, uint32_t b0, uint32_t b1) {
    asm volatile(
        "mma.sync.aligned.m16n8k16.row.col.f32.bf16.bf16.f32 "
        "{%0,%1,%2,%3}, {%4,%5,%6,%7}, {%8,%9}, {%0,%1,%2,%3};"
        : "+f"(d[0]), "+f"(d[1]), "+f"(d[2]), "+f"(d[3])
        : "r"(a[0]), "r"(a[1]), "r"(a[2]), "r"(a[3]), "r"(b0), "r"(b1));
}
#define CP16(dst, src) asm volatile("cp.async.cg.shared.global [%0], [%1], 16;" :: "r"(dst), "l"(src))
#define CPCOMMIT()     asm volatile("cp.async.commit_group;" ::: "memory")
#define CPWAIT0()      asm volatile("cp.async.wait_group 0;" ::: "memory")

// ---------------- prep: split M into bf16 hi/lo, two layouts (zero-padded) ----
__global__ void prep_kernel(const float* __restrict__ mem, int K) {
    int i = blockIdx.x * blockDim.x + threadIdx.x;
    if (i >= MAXK * 64) return;
    int k = i >> 6, d = i & 63;
    float v = (d < DDIM && k < K) ? mem[k * DDIM + d] : 0.f;
    float h = bf16_rt(v);
    __nv_bfloat16 hb = __float2bfloat16(h);
    __nv_bfloat16 lb = __float2bfloat16(v - h);
    gMkA[k * 64 + d] = hb;
    gMkB[k * 64 + d] = lb;
    gMdA[d * MAXK + k] = hb;
    gMdB[d * MAXK + k] = lb;
}

// ---------------- GEMM1 substep: 8 summed scores (3 ks + fp32 fixup d48/49) ---
__device__ __forceinline__ void gemm1_sub(
    float* S, int s, uint32_t KH, uint32_t KL, uint32_t DH, uint32_t DL,
    uint32_t stash_lane,   // SM_STASH + slot*16
    float xf0, float xf1, float xf2, float xf3, int g, int tg)
{
    // reload persistent X fragments from stash (6 conflict-free LDS.128)
    uint32_t Xh[3][4], Xl[3][4];
    #pragma unroll
    for (int ks = 0; ks < 3; ++ks) {
        lds128(Xh[ks], stash_lane + ks * 4096);
        lds128(Xl[ks], stash_lane + (ks + 3) * 4096);
    }
    float A0[4] = {0,0,0,0}, B0[4] = {0,0,0,0}, C0[4] = {0,0,0,0};
    float A1[4] = {0,0,0,0}, B1[4] = {0,0,0,0}, C1[4] = {0,0,0,0};
    uint32_t kb = (uint32_t)(((2 * s) * 8 + g) * (PK * 2) + tg * 4);
    #pragma unroll
    for (int ks = 0; ks < 3; ++ks) {
        uint32_t o = kb + ks * 32;
        uint32_t bh0 = lds32(KH + o);
        uint32_t bh1 = lds32(KH + o + 16);
        uint32_t bl0 = lds32(KL + o);
        uint32_t bl1 = lds32(KL + o + 16);
        mma(A0, Xh[ks], bh0, bh1);          // hi*hi
        mma(B0, Xh[ks], bl0, bl1);          // hi*lo
        mma(C0, Xl[ks], bh0, bh1);          // lo*hi
        uint32_t o1 = o + 8 * (PK * 2);
        uint32_t ch0 = lds32(KH + o1);
        uint32_t ch1 = lds32(KH + o1 + 16);
        uint32_t cl0 = lds32(KL + o1);
        uint32_t cl1 = lds32(KL + o1 + 16);
        mma(A1, Xh[ks], ch0, ch1);
        mma(B1, Xh[ks], cl0, cl1);
        mma(C1, Xl[ks], ch0, ch1);
    }
    // fp32 fixup for dims 48,49 (m reconstructed as hi+lo)
    uint32_t f48 = (uint32_t)(48 * (PK * 2) + s * 32 + tg * 4);
    uint32_t f49 = f48 + PK * 2;
    float m48a, m48b, m49a, m49b, l48a, l48b, l49a, l49b;
    unpack2(lds32(DH + f48), m48a, m48b);  unpack2(lds32(DL + f48), l48a, l48b);
    unpack2(lds32(DH + f49), m49a, m49b);  unpack2(lds32(DL + f49), l49a, l49b);
    float p48a = m48a + l48a, p48b = m48b + l48b;
    float p49a = m49a + l49a, p49b = m49b + l49b;
    float n48a, n48b, n49a, n49b;
    unpack2(lds32(DH + f48 + 16), m48a, m48b);  unpack2(lds32(DL + f48 + 16), l48a, l48b);
    unpack2(lds32(DH + f49 + 16), m49a, m49b);  unpack2(lds32(DL + f49 + 16), l49a, l49b);
    n48a = m48a + l48a;  n48b = m48b + l48b;
    n49a = m49a + l49a;  n49b = m49b + l49b;

    S[0] = A0[0] + B0[0] + C0[0] + xf0 * p48a + xf1 * p49a;
    S[1] = A0[1] + B0[1] + C0[1] + xf0 * p48b + xf1 * p49b;
    S[2] = A0[2] + B0[2] + C0[2] + xf2 * p48a + xf3 * p49a;
    S[3] = A0[3] + B0[3] + C0[3] + xf2 * p48b + xf3 * p49b;
    S[4] = A1[0] + B1[0] + C1[0] + xf0 * n48a + xf1 * n49a;
    S[5] = A1[1] + B1[1] + C1[1] + xf0 * n48b + xf1 * n49b;
    S[6] = A1[2] + B1[2] + C1[2] + xf2 * n48a + xf3 * n49a;
    S[7] = A1[3] + B1[3] + C1[3] + xf2 * n48b + xf3 * n49b;
}

// ---------------- exp + split + pack ------------------------------------------
__device__ __forceinline__ void exp_split(const float* S, uint32_t* ah, uint32_t* al) {
    float e[8], h[8];
    #pragma unroll
    for (int i = 0; i < 8; ++i) { e[i] = __expf(S[i]); h[i] = bf16_rt(e[i]); }
    ah[0] = pack2(h[0], h[1]);  ah[1] = pack2(h[2], h[3]);
    ah[2] = pack2(h[4], h[5]);  ah[3] = pack2(h[6], h[7]);
    al[0] = pack2(e[0] - h[0], e[1] - h[1]);  al[1] = pack2(e[2] - h[2], e[3] - h[3]);
    al[2] = pack2(e[4] - h[4], e[5] - h[5]);  al[3] = pack2(e[6] - h[6], e[7] - h[7]);
}

// ---------------- GEMM2 substep: U[16x56] += S * Md ---------------------------
__device__ __forceinline__ void gemm2_sub(
    float U[7][4], const uint32_t* ah, const uint32_t* al,
    int s, uint32_t DH, uint32_t DL, int g, int tg)
{
    uint32_t db = (uint32_t)(g * (PK * 2) + s * 32 + tg * 4);
    #pragma unroll
    for (int nb = 0; nb < 7; ++nb) {
        uint32_t o = db + nb * 8 * (PK * 2);
        uint32_t bh0 = lds32(DH + o);
        uint32_t bh1 = lds32(DH + o + 16);
        uint32_t bl0 = lds32(DL + o);
        uint32_t bl1 = lds32(DL + o + 16);
        mma(U[nb], ah, bh0, bh1);
        mma(U[nb], al, bh0, bh1);
        mma(U[nb], ah, bl0, bl1);
    }
}

// ---------------- main fused kernel ------------------------------------------
__global__ __launch_bounds__(256, 3)
void memread_mma_kernel(const float* __restrict__ x, float* __restrict__ out, int B, int K) {
    extern __shared__ char smem[];
    const uint32_t sb = smem_u32(smem);
    const int tid = threadIdx.x, wid = tid >> 5, lane = tid & 31;
    const int g = lane >> 2, tg = lane & 3;
    const int row0 = blockIdx.x * TM;

    // ---- prologue: X load, passthrough, hi/lo split into (overlaid) staging --
    for (int w = tid; w < TM * 32; w += 256) {
        int r = w >> 5, dp = w & 31;
        int row = row0 + r;
        float2 v = make_float2(0.f, 0.f);
        if (dp < 25 && row < B) {
            v = *reinterpret_cast<const float2*>(x + (size_t)row * DDIM + dp * 2);
            *reinterpret_cast<float2*>(out + (size_t)row * 100 + dp * 2) = v;
        }
        float hx = bf16_rt(v.x), hy = bf16_rt(v.y);
        uint32_t off = (uint32_t)(r * (PK * 2) + dp * 4);
        sts32(sb + SM_XH + off, pack2(hx, hy));
        sts32(sb + SM_XL + off, pack2(v.x - hx, v.y - hy));
    }
    __syncthreads();

    // ---- build X fragments (dims 0..47) and park them in the stash ----------
    const uint32_t stash_lane = sb + SM_STASH + (uint32_t)tid * 16;
    {
        uint32_t base = (uint32_t)((wid * 16 + g) * (PK * 2) + tg * 4);
        #pragma unroll
        for (int ks = 0; ks < 3; ++ks) {
            uint32_t o = base + ks * 32;
            uint32_t fh[4], fl[4];
            fh[0] = lds32(sb + SM_XH + o);
            fh[1] = lds32(sb + SM_XH + o + 8 * PK * 2);
            fh[2] = lds32(sb + SM_XH + o + 16);
            fh[3] = lds32(sb + SM_XH + o + 8 * PK * 2 + 16);
            fl[0] = lds32(sb + SM_XL + o);
            fl[1] = lds32(sb + SM_XL + o + 8 * PK * 2);
            fl[2] = lds32(sb + SM_XL + o + 16);
            fl[3] = lds32(sb + SM_XL + o + 8 * PK * 2 + 16);
            sts128(stash_lane + ks * 4096, fh);
            sts128(stash_lane + (ks + 3) * 4096, fl);
        }
    }
    // fp32 x for dims 48,49 fixup (rows r1 = wid*16+g, r2 = r1+8)
    const int r1 = row0 + wid * 16 + g;
    const int r2 = r1 + 8;
    float xf0 = 0.f, xf1 = 0.f, xf2 = 0.f, xf3 = 0.f;
    if (r1 < B) { xf0 = x[(size_t)r1 * DDIM + 48]; xf1 = x[(size_t)r1 * DDIM + 49]; }
    if (r2 < B) { xf2 = x[(size_t)r2 * DDIM + 48]; xf3 = x[(size_t)r2 * DDIM + 49]; }
    __syncthreads();                      // staging dead -> becomes tile buffer

    float U[7][4];
    #pragma unroll
    for (int nb = 0; nb < 7; ++nb)
        #pragma unroll
        for (int q = 0; q < 4; ++q) U[nb][q] = 0.f;

    const uint32_t KH = sb + SM_KH, KL = sb + SM_KL;
    const uint32_t DH = sb + SM_DH, DL = sb + SM_DL;
    const int ntiles = (K + TKT - 1) / TKT;

    for (int t = 0; t < ntiles; ++t) {
        // ---- load tile t into the (single) buffer ---------------------------
        #pragma unroll
        for (int c = tid; c < 512; c += 256) {
            int r = c >> 3, j = c & 7;
            uint32_t doff = (uint32_t)(r * (PK * 2) + j * 16);
            const char* sKA = (const char*)(gMkA + (size_t)(t * TKT + r) * 64) + j * 16;
            const char* sKB = (const char*)(gMkB + (size_t)(t * TKT + r) * 64) + j * 16;
            const char* sDA = (const char*)(gMdA + (size_t)r * MAXK + t * TKT) + j * 16;
            const char* sDB = (const char*)(gMdB + (size_t)r * MAXK + t * TKT) + j * 16;
            CP16(KH + doff, sKA);
            CP16(KL + doff, sKB);
            CP16(DH + doff, sDA);
            CP16(DL + doff, sDB);
        }
        CPCOMMIT();
        CPWAIT0();
        __syncthreads();

        // ---- 4 substeps: GEMM1 -> exp -> GEMM2 ------------------------------
        #pragma unroll 1
        for (int s = 0; s < 4; ++s) {
            float S[8];
            gemm1_sub(S, s, KH, KL, DH, DL, stash_lane, xf0, xf1, xf2, xf3, g, tg);
            uint32_t ah[4], al[4];
            exp_split(S, ah, al);
            gemm2_sub(U, ah, al, s, DH, DL, g, tg);
        }
        __syncthreads();                  // all warps done with the buffer
    }

    // ---- writeout U -> out[:, 50:100] ---------------------------------------
    #pragma unroll
    for (int nb = 0; nb < 7; ++nb) {
        int col = nb * 8 + tg * 2;
        if (col < DDIM) {
            if (r1 < B)
                *reinterpret_cast<float2*>(out + (size_t)r1 * 100 + 50 + col) =
                    make_float2(U[nb][0], U[nb][1]);
            if (r2 < B)
                *reinterpret_cast<float2*>(out + (size_t)r2 * 100 + 50 + col) =
                    make_float2(U[nb][2], U[nb][3]);
        }
    }
}

// ---------------- launch -----------------------------------------------------
extern "C" void kernel_launch(void* const* d_in, const int* in_sizes, int n_in,
                              void* d_out, int out_size) {
    const float* x   = (const float*)d_in[0];
    const float* mem = (const float*)d_in[1];
    float* out       = (float*)d_out;
    const int B = in_sizes[0] / DDIM;
    const int K = in_sizes[1] / DDIM;

    cudaFuncSetAttribute(memread_mma_kernel,
                         cudaFuncAttributeMaxDynamicSharedMemorySize, SM_TOTAL);

    prep_kernel<<<(MAXK * 64 + 255) / 256, 256>>>(mem, K);

    const int grid = (B + TM - 1) / TM;
    memread_mma_kernel<<<grid, 256, SM_TOTAL>>>(x, out, B, K);
}

// round 7
// speedup vs baseline: 1.1260x; 1.1260x over previous
#include <cuda_runtime.h>
#include <cuda_bf16.h>
#include <cstdint>

#define DDIM 50
#define MAXK 2048
#define TM   256      // rows per CTA (32 rows per warp, 8 warps)
#define TKT  64       // K-slots per tile
#define PK   72       // smem pitch in bf16 (144B rows)

// ---------------- static device scratch (pre-split M, two layouts) -----------
__device__ __align__(16) __nv_bfloat16 gMkA[MAXK * 64];   // [slot][d] hi
__device__ __align__(16) __nv_bfloat16 gMkB[MAXK * 64];   // [slot][d] lo
__device__ __align__(16) __nv_bfloat16 gMdA[64 * MAXK];   // [d][slot] hi
__device__ __align__(16) __nv_bfloat16 gMdB[64 * MAXK];   // [d][slot] lo

// ---------------- smem layout (bytes) ----------------------------------------
#define ARR      9216                    // 64 rows * 144B
#define SM_KH    0
#define SM_KL    ARR
#define SM_DH    (2 * ARR)
#define SM_DL    (3 * ARR)
#define SM_STASH (4 * ARR)               // 36864
#define SM_TOTAL (SM_STASH + 16 * 4096)  // + 65536 = 102400

// ---------------- helpers ----------------------------------------------------
__device__ __forceinline__ uint32_t smem_u32(const void* p) {
    uint32_t a;
    asm("{ .reg .u64 t; cvta.to.shared.u64 t, %1; cvt.u32.u64 %0, t; }" : "=r"(a) : "l"(p));
    return a;
}
__device__ __forceinline__ void sts128(uint32_t addr, const uint32_t* v) {
    asm volatile("st.shared.v4.b32 [%0], {%1, %2, %3, %4};"
                 :: "r"(addr), "r"(v[0]), "r"(v[1]), "r"(v[2]), "r"(v[3]) : "memory");
}
__device__ __forceinline__ void lds128(uint32_t* v, uint32_t addr) {
    asm("ld.shared.v4.u32 {%0, %1, %2, %3}, [%4];"
        : "=r"(v[0]), "=r"(v[1]), "=r"(v[2]), "=r"(v[3]) : "r"(addr));
}
__device__ __forceinline__ void ldm4(uint32_t* r, uint32_t addr) {
    asm volatile("ldmatrix.sync.aligned.m8n8.x4.shared.b16 {%0,%1,%2,%3}, [%4];"
                 : "=r"(r[0]), "=r"(r[1]), "=r"(r[2]), "=r"(r[3]) : "r"(addr));
}
__device__ __forceinline__ void ldm2(uint32_t* r, uint32_t addr) {
    asm volatile("ldmatrix.sync.aligned.m8n8.x2.shared.b16 {%0,%1}, [%2];"
                 : "=r"(r[0]), "=r"(r[1]) : "r"(addr));
}
__device__ __forceinline__ uint32_t pack2(float lo, float hi) {   // -> bf16x2
    uint32_t r;
    asm("{ .reg .b16 l, h; cvt.rn.bf16.f32 l, %1; cvt.rn.bf16.f32 h, %2; mov.b32 %0, {l, h}; }"
        : "=r"(r) : "f"(lo), "f"(hi));
    return r;
}
__device__ __forceinline__ float bf16_rt(float v) {               // round-trip
    float r;
    asm("{ .reg .b16 t; cvt.rn.bf16.f32 t, %1; cvt.f32.bf16 %0, t; }" : "=f"(r) : "f"(v));
    return r;
}
// D += A * B   (m16n8k16, row.col, bf16 in, f32 accum)
__device__ __forceinline__ void mma(float* d, const uint32_t* a, uint32_t b0, uint32_t b1) {
    asm volatile(
        "mma.sync.aligned.m16n8k16.row.col.f32.bf16.bf16.f32 "
        "{%0,%1,%2,%3}, {%4,%5,%6,%7}, {%8,%9}, {%0,%1,%2,%3};"
        : "+f"(d[0]), "+f"(d[1]), "+f"(d[2]), "+f"(d[3])
        : "r"(a[0]), "r"(a[1]), "r"(a[2]), "r"(a[3]), "r"(b0), "r"(b1));
}
#define CP16(dst, src) asm volatile("cp.async.cg.shared.global [%0], [%1], 16;" :: "r"(dst), "l"(src))
#define CPCOMMIT()     asm volatile("cp.async.commit_group;" ::: "memory")
#define CPWAIT0()      asm volatile("cp.async.wait_group 0;" ::: "memory")

// ---------------- prep: split M into bf16 hi/lo, two layouts (zero-padded) ----
__global__ void prep_kernel(const float* __restrict__ mem, int K) {
    int i = blockIdx.x * blockDim.x + threadIdx.x;
    if (i >= MAXK * 64) return;
    int k = i >> 6, d = i & 63;
    float v = (d < DDIM && k < K) ? mem[k * DDIM + d] : 0.f;
    float h = bf16_rt(v);
    __nv_bfloat16 hb = __float2bfloat16(h);
    __nv_bfloat16 lb = __float2bfloat16(v - h);
    gMkA[k * 64 + d] = hb;
    gMkB[k * 64 + d] = lb;
    gMdA[d * MAXK + k] = hb;
    gMdB[d * MAXK + k] = lb;
}

// ---------------- exp + split + pack (S[8] -> A-fragments) --------------------
__device__ __forceinline__ void exp_split(const float* S, uint32_t* ah, uint32_t* al) {
    float e[8], h[8];
    #pragma unroll
    for (int i = 0; i < 8; ++i) { e[i] = __expf(S[i]); h[i] = bf16_rt(e[i]); }
    ah[0] = pack2(h[0], h[1]);  ah[1] = pack2(h[2], h[3]);
    ah[2] = pack2(h[4], h[5]);  ah[3] = pack2(h[6], h[7]);
    al[0] = pack2(e[0] - h[0], e[1] - h[1]);  al[1] = pack2(e[2] - h[2], e[3] - h[3]);
    al[2] = pack2(e[4] - h[4], e[5] - h[5]);  al[3] = pack2(e[6] - h[6], e[7] - h[7]);
}

// GEMM1 for one 16-row block: 4 ks, 2 n-octets, 3 error-comp chains -> S[8]
__device__ __forceinline__ void gemm1_rb(
    float* S, uint32_t KH, uint32_t KL, uint32_t stash_rb, uint32_t offm, int s)
{
    float Ac0[4] = {0,0,0,0}, Bc0[4] = {0,0,0,0};   // nb0
    float Ac1[4] = {0,0,0,0}, Bc1[4] = {0,0,0,0};   // nb1
    const uint32_t kb = (uint32_t)(s * 2304) + offm;
    #pragma unroll
    for (int ks = 0; ks < 4; ++ks) {
        uint32_t bh[4], bl[4], Ah[4], Al[4];
        ldm4(bh, KH + kb + ks * 32);
        ldm4(bl, KL + kb + ks * 32);
        lds128(Ah, stash_rb + ks * 4096);            // hi frags (part 0)
        lds128(Al, stash_rb + (4 + ks) * 4096);      // lo frags (part 1)
        mma(Ac0, Ah, bh[0], bh[1]);
        mma(Bc0, Ah, bl[0], bl[1]);
        mma(Bc0, Al, bh[0], bh[1]);
        mma(Ac1, Ah, bh[2], bh[3]);
        mma(Bc1, Ah, bl[2], bl[3]);
        mma(Bc1, Al, bh[2], bh[3]);
    }
    #pragma unroll
    for (int q = 0; q < 4; ++q) {
        S[q]     = Ac0[q] + Bc0[q];
        S[4 + q] = Ac1[q] + Bc1[q];
    }
}

// ---------------- main fused kernel ------------------------------------------
__global__ __launch_bounds__(256, 2)
void memread_mma_kernel(const float* __restrict__ x, float* __restrict__ out, int B, int K) {
    extern __shared__ char smem[];
    const uint32_t sb = smem_u32(smem);
    const int tid = threadIdx.x, wid = tid >> 5, lane = tid & 31;
    const int g = lane >> 2, tg = lane & 3;
    const int row0 = blockIdx.x * TM;

    // per-lane ldmatrix row-address offset (shared by GEMM1/GEMM2 patterns):
    // bits: row-in-octet (l&7)*144, k-octet ((l>>3)&1)*16, n-octet ((l>>4)&1)*1152
    const uint32_t offm = (uint32_t)((lane & 7) * 144 + ((lane >> 3) & 1) * 16
                                     + ((lane >> 4) & 1) * 1152);

    // ---- prologue A: passthrough x -> out[:, 0:50] (coalesced float2) -------
    for (int w = tid; w < TM * 32; w += 256) {
        int r = w >> 5, dp = w & 31;
        int row = row0 + r;
        if (dp < 25 && row < B) {
            float2 v = *reinterpret_cast<const float2*>(x + (size_t)row * DDIM + dp * 2);
            *reinterpret_cast<float2*>(out + (size_t)row * 100 + dp * 2) = v;
        }
    }

    // ---- prologue B: gather X A-fragments from global, split, park in stash --
    const uint32_t stash = sb + SM_STASH + (uint32_t)tid * 16;
    {
        #pragma unroll
        for (int rb = 0; rb < 2; ++rb) {
            const int rA = row0 + wid * 32 + rb * 16 + g;
            const int rB = rA + 8;
            #pragma unroll
            for (int ks = 0; ks < 4; ++ks) {
                const int c0 = ks * 16 + 2 * tg;
                const int c1 = c0 + 8;
                float2 z = make_float2(0.f, 0.f);
                float2 vA0 = (c0 < DDIM && rA < B) ? *reinterpret_cast<const float2*>(x + (size_t)rA * DDIM + c0) : z;
                float2 vB0 = (c0 < DDIM && rB < B) ? *reinterpret_cast<const float2*>(x + (size_t)rB * DDIM + c0) : z;
                float2 vA1 = (c1 < DDIM && rA < B) ? *reinterpret_cast<const float2*>(x + (size_t)rA * DDIM + c1) : z;
                float2 vB1 = (c1 < DDIM && rB < B) ? *reinterpret_cast<const float2*>(x + (size_t)rB * DDIM + c1) : z;
                float hA0x = bf16_rt(vA0.x), hA0y = bf16_rt(vA0.y);
                float hB0x = bf16_rt(vB0.x), hB0y = bf16_rt(vB0.y);
                float hA1x = bf16_rt(vA1.x), hA1y = bf16_rt(vA1.y);
                float hB1x = bf16_rt(vB1.x), hB1y = bf16_rt(vB1.y);
                uint32_t hi[4], lo[4];
                hi[0] = pack2(hA0x, hA0y);           // a0 = A[g][k]
                hi[1] = pack2(hB0x, hB0y);           // a1 = A[g+8][k]
                hi[2] = pack2(hA1x, hA1y);           // a2 = A[g][k+8]
                hi[3] = pack2(hB1x, hB1y);           // a3 = A[g+8][k+8]
                lo[0] = pack2(vA0.x - hA0x, vA0.y - hA0y);
                lo[1] = pack2(vB0.x - hB0x, vB0.y - hB0y);
                lo[2] = pack2(vA1.x - hA1x, vA1.y - hA1y);
                lo[3] = pack2(vB1.x - hB1x, vB1.y - hB1y);
                sts128(stash + (uint32_t)((rb * 8 + ks) * 4096), hi);
                sts128(stash + (uint32_t)((rb * 8 + 4 + ks) * 4096), lo);
            }
        }
    }
    __syncthreads();

    float U0[7][4], U1[7][4];
    #pragma unroll
    for (int nb = 0; nb < 7; ++nb)
        #pragma unroll
        for (int q = 0; q < 4; ++q) { U0[nb][q] = 0.f; U1[nb][q] = 0.f; }

    const uint32_t KH = sb + SM_KH, KL = sb + SM_KL;
    const uint32_t DH = sb + SM_DH, DL = sb + SM_DL;
    const int ntiles = (K + TKT - 1) / TKT;

    for (int t = 0; t < ntiles; ++t) {
        // ---- load tile t (4 arrays, 64 rows x 128B each) --------------------
        #pragma unroll
        for (int c = tid; c < 512; c += 256) {
            int r = c >> 3, j = c & 7;
            uint32_t doff = (uint32_t)(r * 144 + j * 16);
            const char* sKA = (const char*)(gMkA + (size_t)(t * TKT + r) * 64) + j * 16;
            const char* sKB = (const char*)(gMkB + (size_t)(t * TKT + r) * 64) + j * 16;
            const char* sDA = (const char*)(gMdA + (size_t)r * MAXK + t * TKT) + j * 16;
            const char* sDB = (const char*)(gMdB + (size_t)r * MAXK + t * TKT) + j * 16;
            CP16(KH + doff, sKA);
            CP16(KL + doff, sKB);
            CP16(DH + doff, sDA);
            CP16(DL + doff, sDB);
        }
        CPCOMMIT();
        CPWAIT0();
        __syncthreads();

        // ---- 4 substeps -----------------------------------------------------
        #pragma unroll 1
        for (int s = 0; s < 4; ++s) {
            // GEMM1 + exp per row-block (sequenced to bound register pressure)
            uint32_t ah0[4], al0[4], ah1[4], al1[4];
            {
                float S[8];
                gemm1_rb(S, KH, KL, stash, offm, s);
                exp_split(S, ah0, al0);
            }
            {
                float S[8];
                gemm1_rb(S, KH, KL, stash + 8 * 4096, offm, s);
                exp_split(S, ah1, al1);
            }
            // GEMM2: U[32 x 56] += S * Md ; B-fragments shared across row-blocks
            const uint32_t db = (uint32_t)(s * 32) + offm;
            #pragma unroll
            for (int i = 0; i < 3; ++i) {
                uint32_t dh[4], dl[4];
                ldm4(dh, DH + (uint32_t)(i * 2304) + db);
                ldm4(dl, DL + (uint32_t)(i * 2304) + db);
                mma(U0[2 * i], ah0, dh[0], dh[1]);
                mma(U0[2 * i], al0, dh[0], dh[1]);
                mma(U0[2 * i], ah0, dl[0], dl[1]);
                mma(U1[2 * i], ah1, dh[0], dh[1]);
                mma(U1[2 * i], al1, dh[0], dh[1]);
                mma(U1[2 * i], ah1, dl[0], dl[1]);
                mma(U0[2 * i + 1], ah0, dh[2], dh[3]);
                mma(U0[2 * i + 1], al0, dh[2], dh[3]);
                mma(U0[2 * i + 1], ah0, dl[2], dl[3]);
                mma(U1[2 * i + 1], ah1, dh[2], dh[3]);
                mma(U1[2 * i + 1], al1, dh[2], dh[3]);
                mma(U1[2 * i + 1], ah1, dl[2], dl[3]);
            }
            {   // nb = 6 (d 48..55; 50..55 are zero-padded)
                uint32_t dh[2], dl[2];
                ldm2(dh, DH + 6 * 1152 + db);
                ldm2(dl, DL + 6 * 1152 + db);
                mma(U0[6], ah0, dh[0], dh[1]);
                mma(U0[6], al0, dh[0], dh[1]);
                mma(U0[6], ah0, dl[0], dl[1]);
                mma(U1[6], ah1, dh[0], dh[1]);
                mma(U1[6], al1, dh[0], dh[1]);
                mma(U1[6], ah1, dl[0], dl[1]);
            }
        }
        __syncthreads();                  // done with tile buffer
    }

    // ---- writeout U -> out[:, 50:100] ---------------------------------------
    #pragma unroll
    for (int rb = 0; rb < 2; ++rb) {
        const int rA = row0 + wid * 32 + rb * 16 + g;
        const int rB = rA + 8;
        float (*U)[4] = rb ? U1 : U0;
        #pragma unroll
        for (int nb = 0; nb < 7; ++nb) {
            int col = nb * 8 + tg * 2;
            if (col < DDIM) {
                if (rA < B)
                    *reinterpret_cast<float2*>(out + (size_t)rA * 100 + 50 + col) =
                        make_float2(U[nb][0], U[nb][1]);
                if (rB < B)
                    *reinterpret_cast<float2*>(out + (size_t)rB * 100 + 50 + col) =
                        make_float2(U[nb][2], U[nb][3]);
            }
        }
    }
}

// ---------------- launch -----------------------------------------------------
extern "C" void kernel_launch(void* const* d_in, const int* in_sizes, int n_in,
                              void* d_out, int out_size) {
    const float* x   = (const float*)d_in[0];
    const float* mem = (const float*)d_in[1];
    float* out       = (float*)d_out;
    const int B = in_sizes[0] / DDIM;
    const int K = in_sizes[1] / DDIM;

    cudaFuncSetAttribute(memread_mma_kernel,
                         cudaFuncAttributeMaxDynamicSharedMemorySize, SM_TOTAL);

    prep_kernel<<<(MAXK * 64 + 255) / 256, 256>>>(mem, K);

    const int grid = (B + TM - 1) / TM;
    memread_mma_kernel<<<grid, 256, SM_TOTAL>>>(x, out, B, K);
}

// round 8
// speedup vs baseline: 1.2954x; 1.1504x over previous
#include <cuda_runtime.h>
#include <cuda_bf16.h>
#include <cuda_fp16.h>
#include <cstdint>

#define DDIM 50
#define MAXK 2048
#define TM   256      // rows per CTA (32 rows per warp, 8 warps)
#define TKT  64       // K-slots per tile

// ---------------- static device scratch (pre-split M) ------------------------
__device__ __align__(16) __nv_bfloat16 gMkA[MAXK * 64];   // [slot][d] hi (GEMM1)
__device__ __align__(16) __nv_bfloat16 gMkB[MAXK * 64];   // [slot][d] lo (GEMM1)
__device__ __align__(16) __half       gMdF[64 * MAXK];    // [d][slot] fp16 (GEMM2)

// ---------------- smem layout (bytes) ----------------------------------------
#define ARR      9216                    // 64 rows * 144B pitch
#define SM_KH    0
#define SM_KL    ARR
#define SM_DF    (2 * ARR)
#define SM_STASH (3 * ARR)               // 27648
#define SM_TOTAL (SM_STASH + 16 * 4096)  // + 65536 = 93184

// ---------------- helpers ----------------------------------------------------
__device__ __forceinline__ uint32_t smem_u32(const void* p) {
    uint32_t a;
    asm("{ .reg .u64 t; cvta.to.shared.u64 t, %1; cvt.u32.u64 %0, t; }" : "=r"(a) : "l"(p));
    return a;
}
__device__ __forceinline__ void sts128(uint32_t addr, const uint32_t* v) {
    asm volatile("st.shared.v4.b32 [%0], {%1, %2, %3, %4};"
                 :: "r"(addr), "r"(v[0]), "r"(v[1]), "r"(v[2]), "r"(v[3]) : "memory");
}
__device__ __forceinline__ void lds128(uint32_t* v, uint32_t addr) {
    asm("ld.shared.v4.u32 {%0, %1, %2, %3}, [%4];"
        : "=r"(v[0]), "=r"(v[1]), "=r"(v[2]), "=r"(v[3]) : "r"(addr));
}
__device__ __forceinline__ void ldm4(uint32_t* r, uint32_t addr) {
    asm volatile("ldmatrix.sync.aligned.m8n8.x4.shared.b16 {%0,%1,%2,%3}, [%4];"
                 : "=r"(r[0]), "=r"(r[1]), "=r"(r[2]), "=r"(r[3]) : "r"(addr));
}
__device__ __forceinline__ void ldm2(uint32_t* r, uint32_t addr) {
    asm volatile("ldmatrix.sync.aligned.m8n8.x2.shared.b16 {%0,%1}, [%2];"
                 : "=r"(r[0]), "=r"(r[1]) : "r"(addr));
}
__device__ __forceinline__ uint32_t pack2(float lo, float hi) {   // -> bf16x2
    uint32_t r;
    asm("{ .reg .b16 l, h; cvt.rn.bf16.f32 l, %1; cvt.rn.bf16.f32 h, %2; mov.b32 %0, {l, h}; }"
        : "=r"(r) : "f"(lo), "f"(hi));
    return r;
}
__device__ __forceinline__ uint32_t packh2(float lo, float hi) {  // -> f16x2
    uint32_t r;
    asm("{ .reg .b16 l, h; cvt.rn.f16.f32 l, %1; cvt.rn.f16.f32 h, %2; mov.b32 %0, {l, h}; }"
        : "=r"(r) : "f"(lo), "f"(hi));
    return r;
}
__device__ __forceinline__ float bf16_rt(float v) {               // round-trip
    float r;
    asm("{ .reg .b16 t; cvt.rn.bf16.f32 t, %1; cvt.f32.bf16 %0, t; }" : "=f"(r) : "f"(v));
    return r;
}
// D += A * B   (m16n8k16, row.col, bf16 in, f32 accum)
__device__ __forceinline__ void mma(float* d, const uint32_t* a, uint32_t b0, uint32_t b1) {
    asm volatile(
        "mma.sync.aligned.m16n8k16.row.col.f32.bf16.bf16.f32 "
        "{%0,%1,%2,%3}, {%4,%5,%6,%7}, {%8,%9}, {%0,%1,%2,%3};"
        : "+f"(d[0]), "+f"(d[1]), "+f"(d[2]), "+f"(d[3])
        : "r"(a[0]), "r"(a[1]), "r"(a[2]), "r"(a[3]), "r"(b0), "r"(b1));
}
// D += A * B   (m16n8k16, row.col, fp16 in, f32 accum)
__device__ __forceinline__ void mmah(float* d, const uint32_t* a, uint32_t b0, uint32_t b1) {
    asm volatile(
        "mma.sync.aligned.m16n8k16.row.col.f32.f16.f16.f32 "
        "{%0,%1,%2,%3}, {%4,%5,%6,%7}, {%8,%9}, {%0,%1,%2,%3};"
        : "+f"(d[0]), "+f"(d[1]), "+f"(d[2]), "+f"(d[3])
        : "r"(a[0]), "r"(a[1]), "r"(a[2]), "r"(a[3]), "r"(b0), "r"(b1));
}
__device__ __forceinline__ float qmax(float v) {   // max across the tg-quad
    v = fmaxf(v, __shfl_xor_sync(0xffffffffu, v, 1));
    v = fmaxf(v, __shfl_xor_sync(0xffffffffu, v, 2));
    return v;
}
#define CP16(dst, src) asm volatile("cp.async.cg.shared.global [%0], [%1], 16;" :: "r"(dst), "l"(src))
#define CPCOMMIT()     asm volatile("cp.async.commit_group;" ::: "memory")
#define CPWAIT0()      asm volatile("cp.async.wait_group 0;" ::: "memory")

// ---------------- prep: split M (bf16 hi/lo K-major) + fp16 D-major -----------
__global__ void prep_kernel(const float* __restrict__ mem, int K) {
    int i = blockIdx.x * blockDim.x + threadIdx.x;
    if (i >= MAXK * 64) return;
    int k = i >> 6, d = i & 63;
    float v = (d < DDIM && k < K) ? mem[k * DDIM + d] : 0.f;
    float h = bf16_rt(v);
    gMkA[k * 64 + d] = __float2bfloat16(h);
    gMkB[k * 64 + d] = __float2bfloat16(v - h);
    gMdF[d * MAXK + k] = __float2half(v);
}

// GEMM1 for one 16-row block: 4 ks, 2 n-octets, 3 error-comp chains -> S[8]
__device__ __forceinline__ void gemm1_rb(
    float* S, uint32_t KH, uint32_t KL, uint32_t stash_rb, uint32_t offm, int s)
{
    float Ac0[4] = {0,0,0,0}, Bc0[4] = {0,0,0,0};   // nb0
    float Ac1[4] = {0,0,0,0}, Bc1[4] = {0,0,0,0};   // nb1
    const uint32_t kb = (uint32_t)(s * 2304) + offm;
    #pragma unroll
    for (int ks = 0; ks < 4; ++ks) {
        uint32_t bh[4], bl[4], Ah[4], Al[4];
        ldm4(bh, KH + kb + ks * 32);
        ldm4(bl, KL + kb + ks * 32);
        lds128(Ah, stash_rb + ks * 4096);            // hi frags
        lds128(Al, stash_rb + (4 + ks) * 4096);      // lo frags
        mma(Ac0, Ah, bh[0], bh[1]);
        mma(Bc0, Ah, bl[0], bl[1]);
        mma(Bc0, Al, bh[0], bh[1]);
        mma(Ac1, Ah, bh[2], bh[3]);
        mma(Bc1, Ah, bl[2], bl[3]);
        mma(Bc1, Al, bh[2], bh[3]);
    }
    #pragma unroll
    for (int q = 0; q < 4; ++q) {
        S[q]     = Ac0[q] + Bc0[q];
        S[4 + q] = Ac1[q] + Bc1[q];
    }
}

// ---------------- main fused kernel ------------------------------------------
__global__ __launch_bounds__(256, 2)
void memread_mma_kernel(const float* __restrict__ x, float* __restrict__ out, int B, int K) {
    extern __shared__ char smem[];
    const uint32_t sb = smem_u32(smem);
    const int tid = threadIdx.x, wid = tid >> 5, lane = tid & 31;
    const int g = lane >> 2, tg = lane & 3;
    const int row0 = blockIdx.x * TM;

    // per-lane ldmatrix row-address offset
    const uint32_t offm = (uint32_t)((lane & 7) * 144 + ((lane >> 3) & 1) * 16
                                     + ((lane >> 4) & 1) * 1152);

    // ---- prologue A: passthrough x -> out[:, 0:50] --------------------------
    for (int w = tid; w < TM * 32; w += 256) {
        int r = w >> 5, dp = w & 31;
        int row = row0 + r;
        if (dp < 25 && row < B) {
            float2 v = *reinterpret_cast<const float2*>(x + (size_t)row * DDIM + dp * 2);
            *reinterpret_cast<float2*>(out + (size_t)row * 100 + dp * 2) = v;
        }
    }

    // ---- prologue B: gather X A-fragments, split, park in stash -------------
    const uint32_t stash = sb + SM_STASH + (uint32_t)tid * 16;
    #pragma unroll
    for (int rb = 0; rb < 2; ++rb) {
        const int rA = row0 + wid * 32 + rb * 16 + g;
        const int rB = rA + 8;
        #pragma unroll
        for (int ks = 0; ks < 4; ++ks) {
            const int c0 = ks * 16 + 2 * tg;
            const int c1 = c0 + 8;
            float2 z = make_float2(0.f, 0.f);
            float2 vA0 = (c0 < DDIM && rA < B) ? *reinterpret_cast<const float2*>(x + (size_t)rA * DDIM + c0) : z;
            float2 vB0 = (c0 < DDIM && rB < B) ? *reinterpret_cast<const float2*>(x + (size_t)rB * DDIM + c0) : z;
            float2 vA1 = (c1 < DDIM && rA < B) ? *reinterpret_cast<const float2*>(x + (size_t)rA * DDIM + c1) : z;
            float2 vB1 = (c1 < DDIM && rB < B) ? *reinterpret_cast<const float2*>(x + (size_t)rB * DDIM + c1) : z;
            float hA0x = bf16_rt(vA0.x), hA0y = bf16_rt(vA0.y);
            float hB0x = bf16_rt(vB0.x), hB0y = bf16_rt(vB0.y);
            float hA1x = bf16_rt(vA1.x), hA1y = bf16_rt(vA1.y);
            float hB1x = bf16_rt(vB1.x), hB1y = bf16_rt(vB1.y);
            uint32_t hi[4], lo[4];
            hi[0] = pack2(hA0x, hA0y);
            hi[1] = pack2(hB0x, hB0y);
            hi[2] = pack2(hA1x, hA1y);
            hi[3] = pack2(hB1x, hB1y);
            lo[0] = pack2(vA0.x - hA0x, vA0.y - hA0y);
            lo[1] = pack2(vB0.x - hB0x, vB0.y - hB0y);
            lo[2] = pack2(vA1.x - hA1x, vA1.y - hA1y);
            lo[3] = pack2(vB1.x - hB1x, vB1.y - hB1y);
            sts128(stash + (uint32_t)((rb * 8 + ks) * 4096), hi);
            sts128(stash + (uint32_t)((rb * 8 + 4 + ks) * 4096), lo);
        }
    }
    __syncthreads();

    float U0[7][4], U1[7][4];
    #pragma unroll
    for (int nb = 0; nb < 7; ++nb)
        #pragma unroll
        for (int q = 0; q < 4; ++q) { U0[nb][q] = 0.f; U1[nb][q] = 0.f; }

    // flash-style running row maxes (rows rA/rB of each 16-row block)
    float mA0 = -1e30f, mB0 = -1e30f, mA1 = -1e30f, mB1 = -1e30f;

    const uint32_t KH = sb + SM_KH, KL = sb + SM_KL, DF = sb + SM_DF;
    const int ntiles = (K + TKT - 1) / TKT;

    for (int t = 0; t < ntiles; ++t) {
        // ---- load tile t (3 arrays, 64 rows x 128B each) --------------------
        #pragma unroll
        for (int c = tid; c < 512; c += 256) {
            int r = c >> 3, j = c & 7;
            uint32_t doff = (uint32_t)(r * 144 + j * 16);
            const char* sKA = (const char*)(gMkA + (size_t)(t * TKT + r) * 64) + j * 16;
            const char* sKB = (const char*)(gMkB + (size_t)(t * TKT + r) * 64) + j * 16;
            const char* sDF = (const char*)(gMdF + (size_t)r * MAXK + t * TKT) + j * 16;
            CP16(KH + doff, sKA);
            CP16(KL + doff, sKB);
            CP16(DF + doff, sDF);
        }
        CPCOMMIT();
        CPWAIT0();
        __syncthreads();

        // ---- 4 substeps -----------------------------------------------------
        #pragma unroll 1
        for (int s = 0; s < 4; ++s) {
            float S0[8], S1[8];
            gemm1_rb(S0, KH, KL, stash, offm, s);
            gemm1_rb(S1, KH, KL, stash + 8 * 4096, offm, s);

            // substep row maxes (uniform within each tg-quad after qmax)
            float sA0 = qmax(fmaxf(fmaxf(S0[0], S0[1]), fmaxf(S0[4], S0[5])));
            float sB0 = qmax(fmaxf(fmaxf(S0[2], S0[3]), fmaxf(S0[6], S0[7])));
            float sA1 = qmax(fmaxf(fmaxf(S1[0], S1[1]), fmaxf(S1[4], S1[5])));
            float sB1 = qmax(fmaxf(fmaxf(S1[2], S1[3]), fmaxf(S1[6], S1[7])));

            bool up = (sA0 > mA0) | (sB0 > mB0) | (sA1 > mA1) | (sB1 > mB1);
            if (__any_sync(0xffffffffu, up)) {        // rare after early tiles
                float nA0 = fmaxf(mA0, sA0), nB0 = fmaxf(mB0, sB0);
                float nA1 = fmaxf(mA1, sA1), nB1 = fmaxf(mB1, sB1);
                float cA0 = __expf(mA0 - nA0), cB0 = __expf(mB0 - nB0);
                float cA1 = __expf(mA1 - nA1), cB1 = __expf(mB1 - nB1);
                #pragma unroll
                for (int nb = 0; nb < 7; ++nb) {
                    U0[nb][0] *= cA0; U0[nb][1] *= cA0;
                    U0[nb][2] *= cB0; U0[nb][3] *= cB0;
                    U1[nb][0] *= cA1; U1[nb][1] *= cA1;
                    U1[nb][2] *= cB1; U1[nb][3] *= cB1;
                }
                mA0 = nA0; mB0 = nB0; mA1 = nA1; mB1 = nB1;
            }

            // s' = exp(S - m_row) in fp16 (always <= 1: no overflow)
            uint32_t ah0[4], ah1[4];
            ah0[0] = packh2(__expf(S0[0] - mA0), __expf(S0[1] - mA0));
            ah0[1] = packh2(__expf(S0[2] - mB0), __expf(S0[3] - mB0));
            ah0[2] = packh2(__expf(S0[4] - mA0), __expf(S0[5] - mA0));
            ah0[3] = packh2(__expf(S0[6] - mB0), __expf(S0[7] - mB0));
            ah1[0] = packh2(__expf(S1[0] - mA1), __expf(S1[1] - mA1));
            ah1[1] = packh2(__expf(S1[2] - mB1), __expf(S1[3] - mB1));
            ah1[2] = packh2(__expf(S1[4] - mA1), __expf(S1[5] - mA1));
            ah1[3] = packh2(__expf(S1[6] - mB1), __expf(S1[7] - mB1));

            // GEMM2: fp16 single pass, U[32 x 56] += s' * Md
            const uint32_t db = (uint32_t)(s * 32) + offm;
            #pragma unroll
            for (int i = 0; i < 3; ++i) {
                uint32_t dh[4];
                ldm4(dh, DF + (uint32_t)(i * 2304) + db);
                mmah(U0[2 * i],     ah0, dh[0], dh[1]);
                mmah(U1[2 * i],     ah1, dh[0], dh[1]);
                mmah(U0[2 * i + 1], ah0, dh[2], dh[3]);
                mmah(U1[2 * i + 1], ah1, dh[2], dh[3]);
            }
            {   // nb = 6 (d 48..55; 50..55 zero-padded)
                uint32_t d2[2];
                ldm2(d2, DF + 6 * 1152 + db);
                mmah(U0[6], ah0, d2[0], d2[1]);
                mmah(U1[6], ah1, d2[0], d2[1]);
            }
        }
        __syncthreads();                  // done with tile buffer
    }

    // ---- writeout U * e^m -> out[:, 50:100] ---------------------------------
    const float eA0 = __expf(mA0), eB0 = __expf(mB0);
    const float eA1 = __expf(mA1), eB1 = __expf(mB1);
    #pragma unroll
    for (int rb = 0; rb < 2; ++rb) {
        const int rA = row0 + wid * 32 + rb * 16 + g;
        const int rB = rA + 8;
        float (*U)[4] = rb ? U1 : U0;
        const float eA = rb ? eA1 : eA0;
        const float eB = rb ? eB1 : eB0;
        #pragma unroll
        for (int nb = 0; nb < 7; ++nb) {
            int col = nb * 8 + tg * 2;
            if (col < DDIM) {
                if (rA < B)
                    *reinterpret_cast<float2*>(out + (size_t)rA * 100 + 50 + col) =
                        make_float2(U[nb][0] * eA, U[nb][1] * eA);
                if (rB < B)
                    *reinterpret_cast<float2*>(out + (size_t)rB * 100 + 50 + col) =
                        make_float2(U[nb][2] * eB, U[nb][3] * eB);
            }
        }
    }
}

// ---------------- launch -----------------------------------------------------
extern "C" void kernel_launch(void* const* d_in, const int* in_sizes, int n_in,
                              void* d_out, int out_size) {
    const float* x   = (const float*)d_in[0];
    const float* mem = (const float*)d_in[1];
    float* out       = (float*)d_out;
    const int B = in_sizes[0] / DDIM;
    const int K = in_sizes[1] / DDIM;

    cudaFuncSetAttribute(memread_mma_kernel,
                         cudaFuncAttributeMaxDynamicSharedMemorySize, SM_TOTAL);

    prep_kernel<<<(MAXK * 64 + 255) / 256, 256>>>(mem, K);

    const int grid = (B + TM - 1) / TM;
    memread_mma_kernel<<<grid, 256, SM_TOTAL>>>(x, out, B, K);
}

// round 9
// speedup vs baseline: 1.5687x; 1.2110x over previous
#include <cuda_runtime.h>
#include <cuda_bf16.h>
#include <cuda_fp16.h>
#include <cstdint>

#define DDIM 50
#define MAXK 2048
#define TM   256      // rows per CTA (32 rows per warp, 8 warps)
#define TKT  64       // K-slots per tile

// ---------------- static device scratch (pre-split M) ------------------------
__device__ __align__(16) __nv_bfloat16 gMkA[MAXK * 64];   // [slot][d] hi (GEMM1)
__device__ __align__(16) __nv_bfloat16 gMkB[MAXK * 64];   // [slot][d] lo (GEMM1)
__device__ __align__(16) __half       gMdF[64 * MAXK];    // [d][slot] fp16 (GEMM2)
__device__ __align__(16) float        gMt[MAXK * 2];      // [slot][2]: m48, m49 fp32

// ---------------- smem layout (bytes) ----------------------------------------
#define ARR      9216                    // 64 rows * 144B pitch
#define SM_KH    0
#define SM_KL    ARR
#define SM_DF    (2 * ARR)
#define SM_STASH (3 * ARR)               // 27648
#define SM_TAIL  (SM_STASH + 65536)      // 93184
#define SM_TOTAL (SM_TAIL + 512)         // 93696

// ---------------- helpers ----------------------------------------------------
__device__ __forceinline__ uint32_t smem_u32(const void* p) {
    uint32_t a;
    asm("{ .reg .u64 t; cvta.to.shared.u64 t, %1; cvt.u32.u64 %0, t; }" : "=r"(a) : "l"(p));
    return a;
}
__device__ __forceinline__ void sts128(uint32_t addr, const uint32_t* v) {
    asm volatile("st.shared.v4.b32 [%0], {%1, %2, %3, %4};"
                 :: "r"(addr), "r"(v[0]), "r"(v[1]), "r"(v[2]), "r"(v[3]) : "memory");
}
__device__ __forceinline__ void lds128(uint32_t* v, uint32_t addr) {
    asm("ld.shared.v4.u32 {%0, %1, %2, %3}, [%4];"
        : "=r"(v[0]), "=r"(v[1]), "=r"(v[2]), "=r"(v[3]) : "r"(addr));
}
__device__ __forceinline__ float2 lds64f(uint32_t addr) {
    float2 v;
    asm("ld.shared.v2.f32 {%0, %1}, [%2];" : "=f"(v.x), "=f"(v.y) : "r"(addr));
    return v;
}
__device__ __forceinline__ void ldm4(uint32_t* r, uint32_t addr) {
    asm volatile("ldmatrix.sync.aligned.m8n8.x4.shared.b16 {%0,%1,%2,%3}, [%4];"
                 : "=r"(r[0]), "=r"(r[1]), "=r"(r[2]), "=r"(r[3]) : "r"(addr));
}
__device__ __forceinline__ void ldm2(uint32_t* r, uint32_t addr) {
    asm volatile("ldmatrix.sync.aligned.m8n8.x2.shared.b16 {%0,%1}, [%2];"
                 : "=r"(r[0]), "=r"(r[1]) : "r"(addr));
}
__device__ __forceinline__ uint32_t pack2(float lo, float hi) {   // -> bf16x2
    uint32_t r;
    asm("{ .reg .b16 l, h; cvt.rn.bf16.f32 l, %1; cvt.rn.bf16.f32 h, %2; mov.b32 %0, {l, h}; }"
        : "=r"(r) : "f"(lo), "f"(hi));
    return r;
}
__device__ __forceinline__ uint32_t packh2(float lo, float hi) {  // -> f16x2
    uint32_t r;
    asm("{ .reg .b16 l, h; cvt.rn.f16.f32 l, %1; cvt.rn.f16.f32 h, %2; mov.b32 %0, {l, h}; }"
        : "=r"(r) : "f"(lo), "f"(hi));
    return r;
}
__device__ __forceinline__ float bf16_rt(float v) {               // round-trip
    float r;
    asm("{ .reg .b16 t; cvt.rn.bf16.f32 t, %1; cvt.f32.bf16 %0, t; }" : "=f"(r) : "f"(v));
    return r;
}
// D += A * B   (m16n8k16, row.col, bf16 in, f32 accum)
__device__ __forceinline__ void mma(float* d, const uint32_t* a, uint32_t b0, uint32_t b1) {
    asm volatile(
        "mma.sync.aligned.m16n8k16.row.col.f32.bf16.bf16.f32 "
        "{%0,%1,%2,%3}, {%4,%5,%6,%7}, {%8,%9}, {%0,%1,%2,%3};"
        : "+f"(d[0]), "+f"(d[1]), "+f"(d[2]), "+f"(d[3])
        : "r"(a[0]), "r"(a[1]), "r"(a[2]), "r"(a[3]), "r"(b0), "r"(b1));
}
// D += A * B   (m16n8k16, row.col, fp16 in, f32 accum)
__device__ __forceinline__ void mmah(float* d, const uint32_t* a, uint32_t b0, uint32_t b1) {
    asm volatile(
        "mma.sync.aligned.m16n8k16.row.col.f32.f16.f16.f32 "
        "{%0,%1,%2,%3}, {%4,%5,%6,%7}, {%8,%9}, {%0,%1,%2,%3};"
        : "+f"(d[0]), "+f"(d[1]), "+f"(d[2]), "+f"(d[3])
        : "r"(a[0]), "r"(a[1]), "r"(a[2]), "r"(a[3]), "r"(b0), "r"(b1));
}
__device__ __forceinline__ float qmax(float v) {   // max across the tg-quad
    v = fmaxf(v, __shfl_xor_sync(0xffffffffu, v, 1));
    v = fmaxf(v, __shfl_xor_sync(0xffffffffu, v, 2));
    return v;
}
#define CP16(dst, src) asm volatile("cp.async.cg.shared.global [%0], [%1], 16;" :: "r"(dst), "l"(src))
#define CPCOMMIT()     asm volatile("cp.async.commit_group;" ::: "memory")
#define CPWAIT0()      asm volatile("cp.async.wait_group 0;" ::: "memory")

// ---------------- prep: M splits + fp16 D-major + fp32 tail -------------------
__global__ void prep_kernel(const float* __restrict__ mem, int K) {
    int i = blockIdx.x * blockDim.x + threadIdx.x;
    if (i >= MAXK * 64) return;
    int k = i >> 6, d = i & 63;
    float v = (d < DDIM && k < K) ? mem[k * DDIM + d] : 0.f;
    float h = bf16_rt(v);
    gMkA[k * 64 + d] = __float2bfloat16(h);
    gMkB[k * 64 + d] = __float2bfloat16(v - h);
    gMdF[d * MAXK + k] = __float2half(v);
    if (d < 2) gMt[k * 2 + d] = (k < K) ? mem[k * DDIM + 48 + d] : 0.f;
}

// GEMM1 both row-blocks: 3 ks, shared B-fragments, 2x independent chains
__device__ __forceinline__ void gemm1_both(
    float* S0, float* S1, uint32_t KH, uint32_t KL,
    uint32_t stash, uint32_t offm, int s)
{
    float a00[4] = {0,0,0,0}, b00[4] = {0,0,0,0};   // rb0 nb0: main, corr
    float a01[4] = {0,0,0,0}, b01[4] = {0,0,0,0};   // rb0 nb1
    float a10[4] = {0,0,0,0}, b10[4] = {0,0,0,0};   // rb1 nb0
    float a11[4] = {0,0,0,0}, b11[4] = {0,0,0,0};   // rb1 nb1
    const uint32_t kb = (uint32_t)(s * 2304) + offm;
    #pragma unroll
    for (int ks = 0; ks < 3; ++ks) {
        uint32_t bh[4], bl[4], Ah0[4], Al0[4], Ah1[4], Al1[4];
        ldm4(bh, KH + kb + ks * 32);
        ldm4(bl, KL + kb + ks * 32);
        lds128(Ah0, stash + ks * 4096);
        lds128(Al0, stash + (4 + ks) * 4096);
        lds128(Ah1, stash + (8 + ks) * 4096);
        lds128(Al1, stash + (12 + ks) * 4096);
        mma(a00, Ah0, bh[0], bh[1]);
        mma(a10, Ah1, bh[0], bh[1]);
        mma(a01, Ah0, bh[2], bh[3]);
        mma(a11, Ah1, bh[2], bh[3]);
        mma(b00, Ah0, bl[0], bl[1]);
        mma(b10, Ah1, bl[0], bl[1]);
        mma(b01, Ah0, bl[2], bl[3]);
        mma(b11, Ah1, bl[2], bl[3]);
        mma(b00, Al0, bh[0], bh[1]);
        mma(b10, Al1, bh[0], bh[1]);
        mma(b01, Al0, bh[2], bh[3]);
        mma(b11, Al1, bh[2], bh[3]);
    }
    #pragma unroll
    for (int q = 0; q < 4; ++q) {
        S0[q]     = a00[q] + b00[q];
        S0[4 + q] = a01[q] + b01[q];
        S1[q]     = a10[q] + b10[q];
        S1[4 + q] = a11[q] + b11[q];
    }
}

// ---------------- main fused kernel ------------------------------------------
__global__ __launch_bounds__(256, 2)
void memread_mma_kernel(const float* __restrict__ x, float* __restrict__ out, int B, int K) {
    extern __shared__ char smem[];
    const uint32_t sb = smem_u32(smem);
    const int tid = threadIdx.x, wid = tid >> 5, lane = tid & 31;
    const int g = lane >> 2, tg = lane & 3;
    const int row0 = blockIdx.x * TM;

    // per-lane ldmatrix row-address offset
    const uint32_t offm = (uint32_t)((lane & 7) * 144 + ((lane >> 3) & 1) * 16
                                     + ((lane >> 4) & 1) * 1152);

    // ---- prologue A: passthrough x -> out[:, 0:50] --------------------------
    for (int w = tid; w < TM * 32; w += 256) {
        int r = w >> 5, dp = w & 31;
        int row = row0 + r;
        if (dp < 25 && row < B) {
            float2 v = *reinterpret_cast<const float2*>(x + (size_t)row * DDIM + dp * 2);
            *reinterpret_cast<float2*>(out + (size_t)row * 100 + dp * 2) = v;
        }
    }

    // ---- prologue B: gather X A-fragments (dims 0..47), split, park in stash -
    const uint32_t stash = sb + SM_STASH + (uint32_t)tid * 16;
    #pragma unroll
    for (int rb = 0; rb < 2; ++rb) {
        const int rA = row0 + wid * 32 + rb * 16 + g;
        const int rB = rA + 8;
        #pragma unroll
        for (int ks = 0; ks < 3; ++ks) {
            const int c0 = ks * 16 + 2 * tg;
            const int c1 = c0 + 8;
            float2 z = make_float2(0.f, 0.f);
            float2 vA0 = (rA < B) ? *reinterpret_cast<const float2*>(x + (size_t)rA * DDIM + c0) : z;
            float2 vB0 = (rB < B) ? *reinterpret_cast<const float2*>(x + (size_t)rB * DDIM + c0) : z;
            float2 vA1 = (rA < B) ? *reinterpret_cast<const float2*>(x + (size_t)rA * DDIM + c1) : z;
            float2 vB1 = (rB < B) ? *reinterpret_cast<const float2*>(x + (size_t)rB * DDIM + c1) : z;
            float hA0x = bf16_rt(vA0.x), hA0y = bf16_rt(vA0.y);
            float hB0x = bf16_rt(vB0.x), hB0y = bf16_rt(vB0.y);
            float hA1x = bf16_rt(vA1.x), hA1y = bf16_rt(vA1.y);
            float hB1x = bf16_rt(vB1.x), hB1y = bf16_rt(vB1.y);
            uint32_t hi[4], lo[4];
            hi[0] = pack2(hA0x, hA0y);
            hi[1] = pack2(hB0x, hB0y);
            hi[2] = pack2(hA1x, hA1y);
            hi[3] = pack2(hB1x, hB1y);
            lo[0] = pack2(vA0.x - hA0x, vA0.y - hA0y);
            lo[1] = pack2(vB0.x - hB0x, vB0.y - hB0y);
            lo[2] = pack2(vA1.x - hA1x, vA1.y - hA1y);
            lo[3] = pack2(vB1.x - hB1x, vB1.y - hB1y);
            sts128(stash + (uint32_t)((rb * 8 + ks) * 4096), hi);
            sts128(stash + (uint32_t)((rb * 8 + 4 + ks) * 4096), lo);
        }
    }
    // fp32 x tail (dims 48,49) for the 4 rows this thread's scores cover
    float xt[2][4];   // [dim48/49][row: A0,B0,A1,B1]
    {
        const int rws[4] = { row0 + wid * 32 + g, row0 + wid * 32 + 8 + g,
                             row0 + wid * 32 + 16 + g, row0 + wid * 32 + 24 + g };
        #pragma unroll
        for (int j = 0; j < 4; ++j) {
            float2 v = (rws[j] < B)
                ? *reinterpret_cast<const float2*>(x + (size_t)rws[j] * DDIM + 48)
                : make_float2(0.f, 0.f);
            xt[0][j] = v.x;  xt[1][j] = v.y;
        }
    }
    __syncthreads();

    float U0[7][4], U1[7][4];
    #pragma unroll
    for (int nb = 0; nb < 7; ++nb)
        #pragma unroll
        for (int q = 0; q < 4; ++q) { U0[nb][q] = 0.f; U1[nb][q] = 0.f; }

    // flash-style running row maxes
    float mA0 = -1e30f, mB0 = -1e30f, mA1 = -1e30f, mB1 = -1e30f;

    const uint32_t KH = sb + SM_KH, KL = sb + SM_KL, DF = sb + SM_DF;
    const uint32_t TAIL = sb + SM_TAIL;
    const int ntiles = (K + TKT - 1) / TKT;

    for (int t = 0; t < ntiles; ++t) {
        // ---- load tile t ----------------------------------------------------
        #pragma unroll
        for (int c = tid; c < 512; c += 256) {
            int r = c >> 3, j = c & 7;
            uint32_t doff = (uint32_t)(r * 144 + j * 16);
            const char* sKA = (const char*)(gMkA + (size_t)(t * TKT + r) * 64) + j * 16;
            const char* sKB = (const char*)(gMkB + (size_t)(t * TKT + r) * 64) + j * 16;
            const char* sDF = (const char*)(gMdF + (size_t)r * MAXK + t * TKT) + j * 16;
            CP16(KH + doff, sKA);
            CP16(KL + doff, sKB);
            CP16(DF + doff, sDF);
        }
        if (tid < 32)   // fp32 tail: 64 slots x (m48, m49) = 512B
            CP16(TAIL + (uint32_t)tid * 16, (const char*)(gMt + (size_t)t * 128) + tid * 16);
        CPCOMMIT();
        CPWAIT0();
        __syncthreads();

        // ---- 4 substeps -----------------------------------------------------
        #pragma unroll 1
        for (int s = 0; s < 4; ++s) {
            float S0[8], S1[8];
            gemm1_both(S0, S1, KH, KL, stash, offm, s);

            // exact fp32 fixup for dims 48,49
            {
                uint32_t ta = TAIL + (uint32_t)(s * 128 + tg * 16);
                float2 t0 = lds64f(ta), t1 = lds64f(ta + 8);
                float2 t2 = lds64f(ta + 64), t3 = lds64f(ta + 72);
                S0[0] += xt[0][0] * t0.x + xt[1][0] * t0.y;
                S0[1] += xt[0][0] * t1.x + xt[1][0] * t1.y;
                S0[2] += xt[0][1] * t0.x + xt[1][1] * t0.y;
                S0[3] += xt[0][1] * t1.x + xt[1][1] * t1.y;
                S0[4] += xt[0][0] * t2.x + xt[1][0] * t2.y;
                S0[5] += xt[0][0] * t3.x + xt[1][0] * t3.y;
                S0[6] += xt[0][1] * t2.x + xt[1][1] * t2.y;
                S0[7] += xt[0][1] * t3.x + xt[1][1] * t3.y;
                S1[0] += xt[0][2] * t0.x + xt[1][2] * t0.y;
                S1[1] += xt[0][2] * t1.x + xt[1][2] * t1.y;
                S1[2] += xt[0][3] * t0.x + xt[1][3] * t0.y;
                S1[3] += xt[0][3] * t1.x + xt[1][3] * t1.y;
                S1[4] += xt[0][2] * t2.x + xt[1][2] * t2.y;
                S1[5] += xt[0][2] * t3.x + xt[1][2] * t3.y;
                S1[6] += xt[0][3] * t2.x + xt[1][3] * t2.y;
                S1[7] += xt[0][3] * t3.x + xt[1][3] * t3.y;
            }

            // substep row maxes
            float sA0 = qmax(fmaxf(fmaxf(S0[0], S0[1]), fmaxf(S0[4], S0[5])));
            float sB0 = qmax(fmaxf(fmaxf(S0[2], S0[3]), fmaxf(S0[6], S0[7])));
            float sA1 = qmax(fmaxf(fmaxf(S1[0], S1[1]), fmaxf(S1[4], S1[5])));
            float sB1 = qmax(fmaxf(fmaxf(S1[2], S1[3]), fmaxf(S1[6], S1[7])));

            bool up = (sA0 > mA0) | (sB0 > mB0) | (sA1 > mA1) | (sB1 > mB1);
            if (__any_sync(0xffffffffu, up)) {
                float nA0 = fmaxf(mA0, sA0), nB0 = fmaxf(mB0, sB0);
                float nA1 = fmaxf(mA1, sA1), nB1 = fmaxf(mB1, sB1);
                float cA0 = __expf(mA0 - nA0), cB0 = __expf(mB0 - nB0);
                float cA1 = __expf(mA1 - nA1), cB1 = __expf(mB1 - nB1);
                #pragma unroll
                for (int nb = 0; nb < 7; ++nb) {
                    U0[nb][0] *= cA0; U0[nb][1] *= cA0;
                    U0[nb][2] *= cB0; U0[nb][3] *= cB0;
                    U1[nb][0] *= cA1; U1[nb][1] *= cA1;
                    U1[nb][2] *= cB1; U1[nb][3] *= cB1;
                }
                mA0 = nA0; mB0 = nB0; mA1 = nA1; mB1 = nB1;
            }

            // s' = exp(S - m_row) in fp16
            uint32_t ah0[4], ah1[4];
            ah0[0] = packh2(__expf(S0[0] - mA0), __expf(S0[1] - mA0));
            ah0[1] = packh2(__expf(S0[2] - mB0), __expf(S0[3] - mB0));
            ah0[2] = packh2(__expf(S0[4] - mA0), __expf(S0[5] - mA0));
            ah0[3] = packh2(__expf(S0[6] - mB0), __expf(S0[7] - mB0));
            ah1[0] = packh2(__expf(S1[0] - mA1), __expf(S1[1] - mA1));
            ah1[1] = packh2(__expf(S1[2] - mB1), __expf(S1[3] - mB1));
            ah1[2] = packh2(__expf(S1[4] - mA1), __expf(S1[5] - mA1));
            ah1[3] = packh2(__expf(S1[6] - mB1), __expf(S1[7] - mB1));

            // GEMM2: fp16 single pass, U[32 x 56] += s' * Md
            const uint32_t db = (uint32_t)(s * 32) + offm;
            #pragma unroll
            for (int i = 0; i < 3; ++i) {
                uint32_t dh[4];
                ldm4(dh, DF + (uint32_t)(i * 2304) + db);
                mmah(U0[2 * i],     ah0, dh[0], dh[1]);
                mmah(U1[2 * i],     ah1, dh[0], dh[1]);
                mmah(U0[2 * i + 1], ah0, dh[2], dh[3]);
                mmah(U1[2 * i + 1], ah1, dh[2], dh[3]);
            }
            {   // nb = 6 (d 48..55; 50..55 zero-padded)
                uint32_t d2[2];
                ldm2(d2, DF + 6 * 1152 + db);
                mmah(U0[6], ah0, d2[0], d2[1]);
                mmah(U1[6], ah1, d2[0], d2[1]);
            }
        }
        __syncthreads();                  // done with tile buffer
    }

    // ---- writeout U * e^m -> out[:, 50:100] ---------------------------------
    const float eA0 = __expf(mA0), eB0 = __expf(mB0);
    const float eA1 = __expf(mA1), eB1 = __expf(mB1);
    #pragma unroll
    for (int rb = 0; rb < 2; ++rb) {
        const int rA = row0 + wid * 32 + rb * 16 + g;
        const int rB = rA + 8;
        float (*U)[4] = rb ? U1 : U0;
        const float eA = rb ? eA1 : eA0;
        const float eB = rb ? eB1 : eB0;
        #pragma unroll
        for (int nb = 0; nb < 7; ++nb) {
            int col = nb * 8 + tg * 2;
            if (col < DDIM) {
                if (rA < B)
                    *reinterpret_cast<float2*>(out + (size_t)rA * 100 + 50 + col) =
                        make_float2(U[nb][0] * eA, U[nb][1] * eA);
                if (rB < B)
                    *reinterpret_cast<float2*>(out + (size_t)rB * 100 + 50 + col) =
                        make_float2(U[nb][2] * eB, U[nb][3] * eB);
            }
        }
    }
}

// ---------------- launch -----------------------------------------------------
extern "C" void kernel_launch(void* const* d_in, const int* in_sizes, int n_in,
                              void* d_out, int out_size) {
    const float* x   = (const float*)d_in[0];
    const float* mem = (const float*)d_in[1];
    float* out       = (float*)d_out;
    const int B = in_sizes[0] / DDIM;
    const int K = in_sizes[1] / DDIM;

    cudaFuncSetAttribute(memread_mma_kernel,
                         cudaFuncAttributeMaxDynamicSharedMemorySize, SM_TOTAL);

    prep_kernel<<<(MAXK * 64 + 255) / 256, 256>>>(mem, K);

    const int grid = (B + TM - 1) / TM;
    memread_mma_kernel<<<grid, 256, SM_TOTAL>>>(x, out, B, K);
}